// round 10
// baseline (speedup 1.0000x reference)
#include <cuda_runtime.h>
#include <math.h>

#define BATCH 4096
#define DIN   64
#define HID   256
#define NB    30
#define NDOF  7
#define OUTC  217
#define NS    51
#define DTC   0.002f
#define AZBZ  56.25f
// ln(float(0.998)) and ln(0.985)
#define LNX   (-0.0020019769f)
#define LNLAM (-0.015113638f)
#define STEPS 500
#define BO    (BATCH * OUTC)

#define NBLK  128
#define NTHR  256

// scratch
__device__ float g_feat[BATCH * HID];
__device__ float g_out217[BO];
__device__ float g_forc[(STEPS + 1) * 32];
__device__ __align__(16) float2 g_coef_t[33 * 64];   // [ch][slot], slot=(s/7)*8+s%7, dup'd; pads stay 0

// grid barrier state (separate cache lines)
__device__ unsigned g_bar_count = 0;
__device__ unsigned g_pad[64];
__device__ unsigned g_bar_sense = 0;

typedef unsigned long long ull;
__device__ __forceinline__ void fma2(ull& d, ull a, ull b) {
    asm("fma.rn.f32x2 %0, %1, %2, %0;" : "+l"(d) : "l"(a), "l"(b));
}
__device__ __forceinline__ float lo32(ull v) { return __uint_as_float((unsigned)v); }
__device__ __forceinline__ float hi32(ull v) { return __uint_as_float((unsigned)(v >> 32)); }

// sense-reversing grid barrier; `my` alternates 1,0 across the two barriers so
// global state returns to 0 every launch (graph-replay safe).
__device__ __forceinline__ void grid_sync(unsigned my) {
    __syncthreads();
    if (threadIdx.x == 0) {
        __threadfence();   // release: publish this block's global writes
        if (atomicAdd(&g_bar_count, 1u) == NBLK - 1u) {
            atomicExch(&g_bar_count, 0u);
            __threadfence();
            atomicExch(&g_bar_sense, my);
        } else {
            while (atomicAdd(&g_bar_sense, 0u) != my) __nanosleep(64);
        }
        __threadfence();   // acquire: CCTL.IVALL -> fresh L1 for this SM
    }
    __syncthreads();
}

// ---------------------------------------------------------------------------
// GEMM1 tile (64x64, K=64): feat = tanh(x @ W_pt + b_pt)
// ---------------------------------------------------------------------------
__device__ __forceinline__ void gemm1_tile(float* sm, const float* __restrict__ X,
                                           const float* __restrict__ Wp,
                                           const float* __restrict__ bp,
                                           int bm, int bn, int tid) {
    float  (*As)[68] = reinterpret_cast<float(*)[68]>(sm);           // [k][m]
    float2 (*Bs)[66] = reinterpret_cast<float2(*)[66]>(sm + 4352);   // [k][n] dup
    __syncthreads();
#pragma unroll
    for (int it = 0; it < 4; it++) {
        int id = tid + it * 256;
        int m = id >> 4, k4 = (id & 15) << 2;
        float4 v = *reinterpret_cast<const float4*>(X + (bm + m) * DIN + k4);
        As[k4 + 0][m] = v.x; As[k4 + 1][m] = v.y;
        As[k4 + 2][m] = v.z; As[k4 + 3][m] = v.w;
    }
#pragma unroll
    for (int it = 0; it < 4; it++) {
        int id = tid + it * 256;
        int k = id >> 4, n4 = (id & 15) << 2;
        float4 v = *reinterpret_cast<const float4*>(Wp + k * HID + bn + n4);
        Bs[k][n4 + 0] = make_float2(v.x, v.x);
        Bs[k][n4 + 1] = make_float2(v.y, v.y);
        Bs[k][n4 + 2] = make_float2(v.z, v.z);
        Bs[k][n4 + 3] = make_float2(v.w, v.w);
    }
    __syncthreads();

    const int ty = tid >> 4, tx = tid & 15;
    ull acc[2][4];
#pragma unroll
    for (int i = 0; i < 2; i++)
#pragma unroll
        for (int j = 0; j < 4; j++) acc[i][j] = 0ull;

#pragma unroll
    for (int k = 0; k < 64; k++) {
        float4 a = *reinterpret_cast<const float4*>(&As[k][ty * 4]);
        ull p0 = *reinterpret_cast<const ull*>(&a.x);
        ull p1 = *reinterpret_cast<const ull*>(&a.z);
#pragma unroll
        for (int j = 0; j < 4; j++) {
            ull b = *reinterpret_cast<const ull*>(&Bs[k][tx + 16 * j]);
            fma2(acc[0][j], p0, b);
            fma2(acc[1][j], p1, b);
        }
    }

#pragma unroll
    for (int j = 0; j < 4; j++) {
        int col = bn + tx + 16 * j;
        float bb = bp[col];
        int r = bm + ty * 4;
        g_feat[(r + 0) * HID + col] = tanhf(lo32(acc[0][j]) + bb);
        g_feat[(r + 1) * HID + col] = tanhf(hi32(acc[0][j]) + bb);
        g_feat[(r + 2) * HID + col] = tanhf(lo32(acc[1][j]) + bb);
        g_feat[(r + 3) * HID + col] = tanhf(hi32(acc[1][j]) + bb);
    }
}

// ---------------------------------------------------------------------------
// GEMM2 tile (64x112, K=256, reg double-buffered): out217 = feat@W_last + b
// ---------------------------------------------------------------------------
__device__ __forceinline__ void gemm2_tile(float* sm, const float* __restrict__ Wl,
                                           const float* __restrict__ bl,
                                           int bm, int bn, int tid) {
    float  (*As)[68]  = reinterpret_cast<float(*)[68]>(sm);            // [k][m]
    float2 (*Bs)[114] = reinterpret_cast<float2(*)[114]>(sm + 2176);   // [k][n] dup
    const int ty = tid >> 4, tx = tid & 15;
    const int am = tid >> 3;
    const int ak4 = (tid & 7) << 2;

    __syncthreads();

    float4 ra[2];
    float rb[14];
#pragma unroll
    for (int it = 0; it < 2; it++)
        ra[it] = *reinterpret_cast<const float4*>(g_feat + (bm + am + it * 32) * HID + ak4);
#pragma unroll
    for (int it = 0; it < 14; it++) {
        int id = tid + it * 256;
        int kk = id / 112, cc = id - kk * 112;
        rb[it] = (bn + cc < OUTC) ? Wl[kk * OUTC + bn + cc] : 0.f;
    }

    ull acc[2][7];
#pragma unroll
    for (int i = 0; i < 2; i++)
#pragma unroll
        for (int j = 0; j < 7; j++) acc[i][j] = 0ull;

    for (int k0 = 0; k0 < HID; k0 += 32) {
#pragma unroll
        for (int it = 0; it < 2; it++) {
            int m = am + it * 32;
            As[ak4 + 0][m] = ra[it].x; As[ak4 + 1][m] = ra[it].y;
            As[ak4 + 2][m] = ra[it].z; As[ak4 + 3][m] = ra[it].w;
        }
#pragma unroll
        for (int it = 0; it < 14; it++) {
            int id = tid + it * 256;
            int kk = id / 112, cc = id - kk * 112;
            Bs[kk][cc] = make_float2(rb[it], rb[it]);
        }
        __syncthreads();

        if (k0 + 32 < HID) {
#pragma unroll
            for (int it = 0; it < 2; it++)
                ra[it] = *reinterpret_cast<const float4*>(
                    g_feat + (bm + am + it * 32) * HID + k0 + 32 + ak4);
#pragma unroll
            for (int it = 0; it < 14; it++) {
                int id = tid + it * 256;
                int kk = id / 112, cc = id - kk * 112;
                rb[it] = (bn + cc < OUTC) ? Wl[(k0 + 32 + kk) * OUTC + bn + cc] : 0.f;
            }
        }

#pragma unroll
        for (int kk = 0; kk < 32; kk++) {
            float4 a = *reinterpret_cast<const float4*>(&As[kk][ty * 4]);
            ull p0 = *reinterpret_cast<const ull*>(&a.x);
            ull p1 = *reinterpret_cast<const ull*>(&a.z);
#pragma unroll
            for (int j = 0; j < 7; j++) {
                ull b = *reinterpret_cast<const ull*>(&Bs[kk][tx + 16 * j]);
                fma2(acc[0][j], p0, b);
                fma2(acc[1][j], p1, b);
            }
        }
        __syncthreads();
    }

#pragma unroll
    for (int j = 0; j < 7; j++) {
        int col = bn + tx + 16 * j;
        if (col < OUTC) {
            float bb = bl[col];
            int r = bm + ty * 4;
            g_out217[(r + 0) * OUTC + col] = lo32(acc[0][j]) + bb;
            g_out217[(r + 1) * OUTC + col] = hi32(acc[0][j]) + bb;
            g_out217[(r + 2) * OUTC + col] = lo32(acc[1][j]) + bb;
            g_out217[(r + 3) * OUTC + col] = hi32(acc[1][j]) + bb;
        }
    }
}

// ---------------------------------------------------------------------------
// Coefficient convolution for sample s (block-local; forcing from g_forc/L2).
// ---------------------------------------------------------------------------
__device__ __forceinline__ void conv_phase(float* sm, int tid, int s) {
    float* kw = sm;    // [STEPS+1]
    const int T = s * 10;
    const int slot = (s / 7) * 8 + (s % 7);

    for (int k = tid; k <= STEPS; k += 256)
        kw[k] = (k == 0) ? 0.f : (float)k * expf(LNLAM * (float)(k - 1));
    __syncthreads();

    const int n = tid >> 3;
    const int part = tid & 7;
    float acc = 0.f;
    if (n < NB) {
        for (int k = part; k < T; k += 8) acc += kw[k] * g_forc[(T - k) * 32 + n];
    } else if (n == NB) {
        for (int k = part; k < T; k += 8) acc += kw[k];
    }
    acc += __shfl_down_sync(0xffffffffu, acc, 4, 8);
    acc += __shfl_down_sync(0xffffffffu, acc, 2, 8);
    acc += __shfl_down_sync(0xffffffffu, acc, 1, 8);

    if (part == 0) {
        if (n < NB) {
            float v = (DTC * DTC) * acc;
            g_coef_t[(3 + n) * 64 + slot] = make_float2(v, v);
        } else if (n == NB) {
            float v = AZBZ * (DTC * DTC) * acc;
            g_coef_t[2 * 64 + slot] = make_float2(v, v);
        }
    }
    if (tid == 254) {
        float v = 0.05f * DTC * kw[T];
        g_coef_t[0 * 64 + slot] = make_float2(v, v);
    }
    if (tid == 255) {
        float v = expf(LNLAM * (float)T) + 0.015f * kw[T];
        g_coef_t[1 * 64 + slot] = make_float2(v, v);
    }
    __syncthreads();
}

// ---------------------------------------------------------------------------
// Rollout phase: one 32-batch tile (224 rows) per block.
// smem floats: scfd[4224] | su[33][224]=7392 | sg[224] | so(6944)/ybuf(11424)
// ---------------------------------------------------------------------------
#define RL_SU   4224
#define RL_SG   (4224 + 7392)          // 11616
#define RL_RG   (11616 + 224)          // 11840
#define MEGA_SMEM ((RL_RG + 11424) * 4)   // 93056 bytes (also covers gemm1 51.2KB)

__device__ __forceinline__ void rollout_phase(float* sm, const float* __restrict__ state,
                                              float* __restrict__ out, int tid, int bid) {
    float2* scfd = reinterpret_cast<float2*>(sm);    // [33][64]
    float*  su   = sm + RL_SU;                       // [33][224]
    float*  sg   = sm + RL_SG;                       // [224]
    float*  so   = sm + RL_RG;                       // [6944]
    float*  ybuf = sm + RL_RG;                       // [11424] (after U build)
    const int bbase = bid * 32;

    __syncthreads();
    // scfd copy (1056 float4) + so load (1736 float4)
    {
        const float4* src = reinterpret_cast<const float4*>(g_coef_t);
        float4* dst = reinterpret_cast<float4*>(scfd);
        for (int i = tid; i < 1056; i += 256) dst[i] = src[i];
        const float4* p0 = reinterpret_cast<const float4*>(g_out217 + bbase * OUTC);
        float4* d = reinterpret_cast<float4*>(so);
        for (int i = tid; i < 1736; i += 256) d[i] = p0[i];
    }
    __syncthreads();

    if (tid < 224) {
        int b = tid / NDOF, dof = tid - b * NDOF;
        float y0 = state[bbase * NDOF + tid];
        float goal = so[b * OUTC + dof];
        su[1 * 224 + tid] = y0;
        su[2 * 224 + tid] = goal;
        sg[tid] = goal - y0;
    }
    __syncthreads();

    // U build: 896 (g, r) slots
    for (int idx = tid; idx < 896; idx += 256) {
        int g = idx / 224, r = idx - g * 224;
        int b = r / NDOF, dof = r - b * NDOF;
        float sgr = sg[r];
        const float* wsrc = so + b * OUTC + NDOF + dof * NB + g;
        float* udst = su + (3 + g) * 224 + r;
#pragma unroll
        for (int i = 0; i < 8; i++) {
            int nn = g + 4 * i;
            if (nn < NB) udst[4 * i * 224] = wsrc[4 * i] * sgr;
        }
    }
    __syncthreads();

    // contraction: thread = (row-oct ro, sample-group grp); 28 fma2 chains
    const bool active = tid < 224;
    const int grp = tid / 28;
    const int ro  = tid - grp * 28;
    ull acc[4][7];
    if (active) {
        const float2* cfb = scfd + grp * 8;
        const float*  ubase = su + ro * 8;
        {   // alpha init (ch 0, u == 1)
            const float4* c4 = reinterpret_cast<const float4*>(cfb);
            float4 c0 = c4[0], c1 = c4[1], c2 = c4[2], c3 = c4[3];
            ull a[7];
            a[0] = *reinterpret_cast<const ull*>(&c0.x);
            a[1] = *reinterpret_cast<const ull*>(&c0.z);
            a[2] = *reinterpret_cast<const ull*>(&c1.x);
            a[3] = *reinterpret_cast<const ull*>(&c1.z);
            a[4] = *reinterpret_cast<const ull*>(&c2.x);
            a[5] = *reinterpret_cast<const ull*>(&c2.z);
            a[6] = *reinterpret_cast<const ull*>(&c3.x);
#pragma unroll
            for (int p = 0; p < 4; p++)
#pragma unroll
                for (int q = 0; q < 7; q++) acc[p][q] = a[q];
        }
#pragma unroll
        for (int ch = 1; ch < 33; ch++) {
            float4 ua = *reinterpret_cast<const float4*>(ubase + ch * 224);
            float4 ub = *reinterpret_cast<const float4*>(ubase + ch * 224 + 4);
            ull u0 = *reinterpret_cast<const ull*>(&ua.x);
            ull u1 = *reinterpret_cast<const ull*>(&ua.z);
            ull u2 = *reinterpret_cast<const ull*>(&ub.x);
            ull u3 = *reinterpret_cast<const ull*>(&ub.z);
            const float4* c4 = reinterpret_cast<const float4*>(cfb + ch * 64);
            float4 c0 = c4[0], c1 = c4[1], c2 = c4[2], c3 = c4[3];
            ull b[7];
            b[0] = *reinterpret_cast<const ull*>(&c0.x);
            b[1] = *reinterpret_cast<const ull*>(&c0.z);
            b[2] = *reinterpret_cast<const ull*>(&c1.x);
            b[3] = *reinterpret_cast<const ull*>(&c1.z);
            b[4] = *reinterpret_cast<const ull*>(&c2.x);
            b[5] = *reinterpret_cast<const ull*>(&c2.z);
            b[6] = *reinterpret_cast<const ull*>(&c3.x);
#pragma unroll
            for (int q = 0; q < 7; q++) {
                fma2(acc[0][q], u0, b[q]);
                fma2(acc[1][q], u1, b[q]);
                fma2(acc[2][q], u2, b[q]);
                fma2(acc[3][q], u3, b[q]);
            }
        }
    }
    __syncthreads();    // so -> ybuf reuse

    if (active) {
        const int s0 = grp * 7;
        const int cnt = (grp == 7) ? 2 : 7;
#pragma unroll
        for (int p = 0; p < 4; p++) {
#pragma unroll
            for (int half = 0; half < 2; half++) {
                int row = ro * 8 + 2 * p + half;
                int b = row / NDOF, dof = row - b * NDOF;
                float* yb = ybuf + b * (NS * NDOF) + dof + s0 * NDOF;
#pragma unroll
                for (int q = 0; q < 7; q++) {
                    if (q < cnt) {
                        float v = half ? hi32(acc[p][q]) : lo32(acc[p][q]);
                        yb[q * NDOF] = v;
                    }
                }
            }
        }
    }
    __syncthreads();

    // contiguous output store: 2856 float4
    {
        const float4* s4 = reinterpret_cast<const float4*>(ybuf);
        float4* d4 = reinterpret_cast<float4*>(out + (size_t)bid * 11424);
        for (int i = tid; i < 2856; i += 256) d4[i] = s4[i];
    }
}

// ---------------------------------------------------------------------------
// Megakernel: P0 forcing+gemm1 | sync | P1 conv+gemm2 | sync | P2 rollout
// ---------------------------------------------------------------------------
__global__ __launch_bounds__(NTHR) void mega_kernel(
    const float* __restrict__ x, const float* __restrict__ state,
    const float* __restrict__ Wp, const float* __restrict__ bp,
    const float* __restrict__ Wl, const float* __restrict__ bl,
    const float* __restrict__ c, const float* __restrict__ h,
    float* __restrict__ out)
{
    extern __shared__ __align__(16) float sm[];
    const int tid = threadIdx.x;
    const int bid = blockIdx.x;

    // P0a: forcing table (global threads 1..500)
    {
        int gt = bid * NTHR + tid;
        if (gt >= 1 && gt <= STEPS) {
            float xv = expf(LNX * (float)gt);
            float psi[NB];
            float S = 0.f;
#pragma unroll
            for (int n = 0; n < NB; n++) {
                float d = xv - c[n];
                float p = expf(-h[n] * d * d);
                psi[n] = p;
                S += p;
            }
            float sc2 = xv / S;
#pragma unroll
            for (int n = 0; n < NB; n++) g_forc[gt * 32 + n] = psi[n] * sc2;
        }
    }
    // P0b: gemm1, 2 tiles per block (256 tiles total)
#pragma unroll
    for (int i = 0; i < 2; i++) {
        int t = bid * 2 + i;
        gemm1_tile(sm, x, Wp, bp, (t & 63) * 64, (t >> 6) * 64, tid);
    }

    grid_sync(1u);

    // P1a: coefficient convolutions (blocks 0..50)
    if (bid < 51) conv_phase(sm, tid, bid);
    // P1b: gemm2, 1 tile per block (128 tiles)
    gemm2_tile(sm, Wl, bl, (bid >> 1) * 64, (bid & 1) * 112, tid);

    grid_sync(0u);

    // P2: rollout, one 32-batch tile per block
    rollout_phase(sm, state, out, tid, bid);
}

// ---------------------------------------------------------------------------
extern "C" void kernel_launch(void* const* d_in, const int* in_sizes, int n_in,
                              void* d_out, int out_size) {
    const float* x      = (const float*)d_in[0];
    const float* state  = (const float*)d_in[1];
    const float* W_pt   = (const float*)d_in[2];
    const float* b_pt   = (const float*)d_in[3];
    const float* W_last = (const float*)d_in[4];
    const float* b_last = (const float*)d_in[5];
    const float* c      = (const float*)d_in[6];
    const float* h      = (const float*)d_in[7];
    float* out = (float*)d_out;

    static int init_done = 0;
    if (!init_done) {
        cudaFuncSetAttribute(mega_kernel, cudaFuncAttributeMaxDynamicSharedMemorySize,
                             MEGA_SMEM);
        init_done = 1;
    }

    mega_kernel<<<NBLK, NTHR, MEGA_SMEM>>>(x, state, W_pt, b_pt, W_last, b_last,
                                           c, h, out);
}

// round 11
// speedup vs baseline: 1.4227x; 1.4227x over previous
#include <cuda_runtime.h>
#include <math.h>

#define BATCH 4096
#define DIN   64
#define HID   256
#define NB    30
#define NDOF  7
#define OUTC  217
#define NS    51
#define DTC   0.002f
#define AZBZ  56.25f
// ln(float(0.998)) and ln(0.985)
#define LNX   (-0.0020019769f)
#define LNLAM (-0.015113638f)
#define GW    501
#define BO    (BATCH * OUTC)

__device__ float g_feat[BATCH * HID];
__device__ float g_out217[2 * BO];       // two split-K partials
// coefficients, transposed [ch][slot], slot=(s/7)*8+s%7, duplicated as float2;
// padding slots never written -> stay 0 (static zero-init).
__device__ __align__(16) float2 g_coef_t[33 * 64];

typedef unsigned long long ull;
__device__ __forceinline__ void fma2(ull& d, ull a, ull b) {
    asm("fma.rn.f32x2 %0, %1, %2, %0;" : "+l"(d) : "l"(a), "l"(b));
}
__device__ __forceinline__ float lo32(ull v) { return __uint_as_float((unsigned)v); }
__device__ __forceinline__ float hi32(ull v) { return __uint_as_float((unsigned)(v >> 32)); }

// --- PDL primitives -------------------------------------------------------
__device__ __forceinline__ void pdl_wait() {
    asm volatile("griddepcontrol.wait;" ::: "memory");
}
__device__ __forceinline__ void pdl_trigger() {
    asm volatile("griddepcontrol.launch_dependents;" ::: "memory");
}

// ---------------------------------------------------------------------------
// K1: gemm1 (blocks 0..255) + fused forcing/coefficient (blocks 256..306).
// gemm1: feat = tanh(x @ W_pt + b_pt), 64x64 tiles.
// coef:  per-sample forcing + convolution -> g_coef_t.
// ---------------------------------------------------------------------------
#define K1_SMEM ((NB * GW + GW + 2 * NB) * 4)   // 62364 B (covers gemm1's 51.2KB)

__global__ __launch_bounds__(256) void k1_kernel(const float* __restrict__ X,
                                                 const float* __restrict__ Wp,
                                                 const float* __restrict__ bp,
                                                 const float* __restrict__ c,
                                                 const float* __restrict__ h) {
    extern __shared__ __align__(16) float sm[];
    const int tid = threadIdx.x;
    const int bid = blockIdx.x;

    if (bid < 256) {
        // ---- gemm1 tile ----
        float  (*As)[68] = reinterpret_cast<float(*)[68]>(sm);          // [k][m]
        float2 (*Bs)[66] = reinterpret_cast<float2(*)[66]>(sm + 4352);  // [k][n] dup
        const int bm = (bid & 63) * 64;
        const int bn = (bid >> 6) * 64;

#pragma unroll
        for (int it = 0; it < 4; it++) {
            int id = tid + it * 256;
            int m = id >> 4, k4 = (id & 15) << 2;
            float4 v = *reinterpret_cast<const float4*>(X + (bm + m) * DIN + k4);
            As[k4 + 0][m] = v.x; As[k4 + 1][m] = v.y;
            As[k4 + 2][m] = v.z; As[k4 + 3][m] = v.w;
        }
#pragma unroll
        for (int it = 0; it < 4; it++) {
            int id = tid + it * 256;
            int k = id >> 4, n4 = (id & 15) << 2;
            float4 v = *reinterpret_cast<const float4*>(Wp + k * HID + bn + n4);
            Bs[k][n4 + 0] = make_float2(v.x, v.x);
            Bs[k][n4 + 1] = make_float2(v.y, v.y);
            Bs[k][n4 + 2] = make_float2(v.z, v.z);
            Bs[k][n4 + 3] = make_float2(v.w, v.w);
        }
        __syncthreads();

        const int ty = tid >> 4, tx = tid & 15;
        ull acc[2][4];
#pragma unroll
        for (int i = 0; i < 2; i++)
#pragma unroll
            for (int j = 0; j < 4; j++) acc[i][j] = 0ull;

#pragma unroll
        for (int k = 0; k < 64; k++) {
            float4 a = *reinterpret_cast<const float4*>(&As[k][ty * 4]);
            ull p0 = *reinterpret_cast<const ull*>(&a.x);
            ull p1 = *reinterpret_cast<const ull*>(&a.z);
#pragma unroll
            for (int j = 0; j < 4; j++) {
                ull b = *reinterpret_cast<const ull*>(&Bs[k][tx + 16 * j]);
                fma2(acc[0][j], p0, b);
                fma2(acc[1][j], p1, b);
            }
        }

#pragma unroll
        for (int j = 0; j < 4; j++) {
            int col = bn + tx + 16 * j;
            float bb = bp[col];
            int r = bm + ty * 4;
            g_feat[(r + 0) * HID + col] = tanhf(lo32(acc[0][j]) + bb);
            g_feat[(r + 1) * HID + col] = tanhf(hi32(acc[0][j]) + bb);
            g_feat[(r + 2) * HID + col] = tanhf(lo32(acc[1][j]) + bb);
            g_feat[(r + 3) * HID + col] = tanhf(hi32(acc[1][j]) + bb);
        }
    } else {
        // ---- coef block for sample s ----
        float* g  = sm;                 // [NB][GW]
        float* kw = g + NB * GW;        // [GW]
        float* sc = kw + GW;            // [NB]
        float* sh = sc + NB;            // [NB]

        const int s = bid - 256;
        const int T = s * 10;
        const int slot = (s / 7) * 8 + (s % 7);

        if (tid < NB) { sc[tid] = c[tid]; sh[tid] = h[tid]; }
        for (int k = tid; k <= T; k += 256)
            kw[k] = (k == 0) ? 0.f : (float)k * expf(LNLAM * (float)(k - 1));
        __syncthreads();

        for (int i = tid + 1; i < T; i += 256) {
            float x = expf(LNX * (float)i);
            float psi[NB];
            float S = 0.f;
#pragma unroll
            for (int n = 0; n < NB; n++) {
                float d = x - sc[n];
                float p = expf(-sh[n] * d * d);
                psi[n] = p;
                S += p;
            }
            float scale = x / S;
#pragma unroll
            for (int n = 0; n < NB; n++) g[n * GW + i] = psi[n] * scale;
        }
        __syncthreads();

        const int n = tid >> 3;
        const int part = tid & 7;
        float acc = 0.f;
        if (n < NB) {
            const float* gn = g + n * GW;
            for (int k = part; k < T; k += 8) acc += kw[k] * gn[T - k];
        } else if (n == NB) {
            for (int k = part; k < T; k += 8) acc += kw[k];
        }
        acc += __shfl_down_sync(0xffffffffu, acc, 4, 8);
        acc += __shfl_down_sync(0xffffffffu, acc, 2, 8);
        acc += __shfl_down_sync(0xffffffffu, acc, 1, 8);

        if (part == 0) {
            if (n < NB) {
                float v = (DTC * DTC) * acc;
                g_coef_t[(3 + n) * 64 + slot] = make_float2(v, v);
            } else if (n == NB) {
                float v = AZBZ * (DTC * DTC) * acc;
                g_coef_t[2 * 64 + slot] = make_float2(v, v);
            }
        }
        if (tid == 254) {
            float v = 0.05f * DTC * kw[T];
            g_coef_t[0 * 64 + slot] = make_float2(v, v);
        }
        if (tid == 255) {
            float v = expf(LNLAM * (float)T) + 0.015f * kw[T];
            g_coef_t[1 * 64 + slot] = make_float2(v, v);
        }
    }
    pdl_trigger();
}

// ---------------------------------------------------------------------------
// K2: GEMM2 (split-K x2): partial[z] = feat[:, z*128:(z+1)*128] @ Wl[z half].
// B-fragment prefetch happens BEFORE pdl_wait (pure input) -> overlaps K1 tail.
// ---------------------------------------------------------------------------
__global__ __launch_bounds__(256) void gemm2_kernel(const float* __restrict__ Wl,
                                                    const float* __restrict__ bl) {
    __shared__ __align__(16) float  As[32][68];   // [k][m]
    __shared__ float2 Bs[32][114];                // [k][n] duplicated
    const int tid = threadIdx.x;
    const int bm = blockIdx.x * 64;
    const int bn = blockIdx.y * 112;
    const int z  = blockIdx.z;
    const int kbase = z * 128;
    const int ty = tid >> 4, tx = tid & 15;

    const int am = tid >> 3;
    const int ak4 = (tid & 7) << 2;

    float4 ra[2];
    float rb[14];

    // B prefetch (input only) — before the PDL wait
#pragma unroll
    for (int it = 0; it < 14; it++) {
        int id = tid + it * 256;
        int kk = id / 112, cc = id - kk * 112;
        rb[it] = (bn + cc < OUTC) ? Wl[(kbase + kk) * OUTC + bn + cc] : 0.f;
    }

    pdl_wait();   // feat (K1 output) valid from here

#pragma unroll
    for (int it = 0; it < 2; it++)
        ra[it] = *reinterpret_cast<const float4*>(
            g_feat + (bm + am + it * 32) * HID + kbase + ak4);

    ull acc[2][7];
#pragma unroll
    for (int i = 0; i < 2; i++)
#pragma unroll
        for (int j = 0; j < 7; j++) acc[i][j] = 0ull;

    for (int k0 = 0; k0 < 128; k0 += 32) {
#pragma unroll
        for (int it = 0; it < 2; it++) {
            int m = am + it * 32;
            As[ak4 + 0][m] = ra[it].x; As[ak4 + 1][m] = ra[it].y;
            As[ak4 + 2][m] = ra[it].z; As[ak4 + 3][m] = ra[it].w;
        }
#pragma unroll
        for (int it = 0; it < 14; it++) {
            int id = tid + it * 256;
            int kk = id / 112, cc = id - kk * 112;
            Bs[kk][cc] = make_float2(rb[it], rb[it]);
        }
        __syncthreads();

        if (k0 + 32 < 128) {
#pragma unroll
            for (int it = 0; it < 2; it++)
                ra[it] = *reinterpret_cast<const float4*>(
                    g_feat + (bm + am + it * 32) * HID + kbase + k0 + 32 + ak4);
#pragma unroll
            for (int it = 0; it < 14; it++) {
                int id = tid + it * 256;
                int kk = id / 112, cc = id - kk * 112;
                rb[it] = (bn + cc < OUTC)
                           ? Wl[(kbase + k0 + 32 + kk) * OUTC + bn + cc] : 0.f;
            }
        }

#pragma unroll
        for (int kk = 0; kk < 32; kk++) {
            float4 a = *reinterpret_cast<const float4*>(&As[kk][ty * 4]);
            ull p0 = *reinterpret_cast<const ull*>(&a.x);
            ull p1 = *reinterpret_cast<const ull*>(&a.z);
#pragma unroll
            for (int j = 0; j < 7; j++) {
                ull b = *reinterpret_cast<const ull*>(&Bs[kk][tx + 16 * j]);
                fma2(acc[0][j], p0, b);
                fma2(acc[1][j], p1, b);
            }
        }
        __syncthreads();
    }

    float* outp = g_out217 + z * BO;
#pragma unroll
    for (int j = 0; j < 7; j++) {
        int col = bn + tx + 16 * j;
        if (col < OUTC) {
            float bb = (z == 0) ? bl[col] : 0.f;
            int r = bm + ty * 4;
            outp[(r + 0) * OUTC + col] = lo32(acc[0][j]) + bb;
            outp[(r + 1) * OUTC + col] = hi32(acc[0][j]) + bb;
            outp[(r + 2) * OUTC + col] = lo32(acc[1][j]) + bb;
            outp[(r + 3) * OUTC + col] = hi32(acc[1][j]) + bb;
        }
    }
    pdl_trigger();
}

// ---------------------------------------------------------------------------
// K3: rollout v5 (R9-proven). Block = 8 batches (56 rows), 512 blocks.
// ---------------------------------------------------------------------------
#define RB_BATCH 8
#define RB_ROWS  56
#define RB_OUTF  (RB_BATCH * OUTC)            // 1736
#define RB_YF    (RB_BATCH * NS * NDOF)       // 2856
#define RB_SU    4224
#define RB_SG    (4224 + 1848)                // 6072
#define RB_RG    (6072 + 56)                  // 6128
#define RB_SMEM  ((RB_RG + RB_YF) * 4)        // 35936 bytes

__global__ __launch_bounds__(256) void rollout_kernel(const float* __restrict__ state,
                                                      float* __restrict__ out) {
    extern __shared__ __align__(16) float sm[];
    float2* scfd = reinterpret_cast<float2*>(sm);   // [33][64] slots
    float*  su   = sm + RB_SU;                      // [33][56]
    float*  sg   = sm + RB_SG;                      // [56]
    float*  so   = sm + RB_RG;                      // [1736]
    float*  ybuf = sm + RB_RG;                      // [2856] (after U build)

    const int tid = threadIdx.x;
    const int bbase = blockIdx.x * RB_BATCH;

    pdl_wait();   // g_coef_t (K1, transitive) and g_out217 (K2) valid

    // scfd fill: pure vector copy, 33*64 float2 = 1056 float4
    {
        const float4* src = reinterpret_cast<const float4*>(g_coef_t);
        float4* dst = reinterpret_cast<float4*>(scfd);
        for (int i = tid; i < 1056; i += 256) dst[i] = src[i];
    }
    // A: contiguous float4 load of both partials, summed
    {
        const float4* p0 = reinterpret_cast<const float4*>(g_out217 + bbase * OUTC);
        const float4* p1 = reinterpret_cast<const float4*>(g_out217 + BO + bbase * OUTC);
        float4* d = reinterpret_cast<float4*>(so);
        for (int i = tid; i < RB_OUTF / 4; i += 256) {
            float4 a = p0[i], b = p1[i];
            d[i] = make_float4(a.x + b.x, a.y + b.y, a.z + b.z, a.w + b.w);
        }
    }
    __syncthreads();

    // y0 / goal / gy0
    if (tid < RB_ROWS) {
        int b = tid / NDOF, dof = tid - b * NDOF;
        float y0 = state[bbase * NDOF + tid];
        float goal = so[b * OUTC + dof];
        su[1 * RB_ROWS + tid] = y0;
        su[2 * RB_ROWS + tid] = goal;
        sg[tid] = goal - y0;
    }
    __syncthreads();

    // U-build
    if (tid < 4 * RB_ROWS) {
        const int g = tid / RB_ROWS;
        const int r = tid - g * RB_ROWS;
        const int b = r / NDOF, dof = r - b * NDOF;
        const float sgr = sg[r];
        const float* wsrc = so + b * OUTC + NDOF + dof * NB + g;
        float* udst = su + (3 + g) * RB_ROWS + r;
#pragma unroll
        for (int i = 0; i < 8; i++) {
            int n = g + 4 * i;
            if (n < NB) udst[4 * i * RB_ROWS] = wsrc[4 * i] * sgr;
        }
    }
    __syncthreads();

    // contraction
    if (tid < 224) {
        const int grp = tid / 28;
        const int rp  = tid - grp * 28;
        const float2* cfb = scfd + grp * 8;
        const float*  ub  = su + rp * 2;

        ull acc[7];
        {
            const float4* c4 = reinterpret_cast<const float4*>(cfb);
            float4 c0 = c4[0], c1 = c4[1], c2 = c4[2], c3 = c4[3];
            acc[0] = *reinterpret_cast<const ull*>(&c0.x);
            acc[1] = *reinterpret_cast<const ull*>(&c0.z);
            acc[2] = *reinterpret_cast<const ull*>(&c1.x);
            acc[3] = *reinterpret_cast<const ull*>(&c1.z);
            acc[4] = *reinterpret_cast<const ull*>(&c2.x);
            acc[5] = *reinterpret_cast<const ull*>(&c2.z);
            acc[6] = *reinterpret_cast<const ull*>(&c3.x);
        }
#pragma unroll
        for (int ch = 1; ch < 33; ch++) {
            ull u = *reinterpret_cast<const ull*>(ub + ch * RB_ROWS);
            const float4* c4 = reinterpret_cast<const float4*>(cfb + ch * 64);
            float4 c0 = c4[0], c1 = c4[1], c2 = c4[2], c3 = c4[3];
            fma2(acc[0], u, *reinterpret_cast<const ull*>(&c0.x));
            fma2(acc[1], u, *reinterpret_cast<const ull*>(&c0.z));
            fma2(acc[2], u, *reinterpret_cast<const ull*>(&c1.x));
            fma2(acc[3], u, *reinterpret_cast<const ull*>(&c1.z));
            fma2(acc[4], u, *reinterpret_cast<const ull*>(&c2.x));
            fma2(acc[5], u, *reinterpret_cast<const ull*>(&c2.z));
            fma2(acc[6], u, *reinterpret_cast<const ull*>(&c3.x));
        }
        __syncthreads();   // so -> ybuf reuse

        const int s0 = grp * 7;
        const int cnt = (grp == 7) ? 2 : 7;
#pragma unroll
        for (int p = 0; p < 2; p++) {
            int row = rp * 2 + p;
            int b = row / NDOF, dof = row - b * NDOF;
            float* yb = ybuf + b * (NS * NDOF) + dof + s0 * NDOF;
#pragma unroll
            for (int q = 0; q < 7; q++) {
                if (q < cnt) {
                    float v = p ? hi32(acc[q]) : lo32(acc[q]);
                    yb[q * NDOF] = v;
                }
            }
        }
    } else {
        __syncthreads();
    }
    __syncthreads();

    // contiguous output store
    {
        const float4* s4 = reinterpret_cast<const float4*>(ybuf);
        float4* d4 = reinterpret_cast<float4*>(out + (size_t)blockIdx.x * RB_YF);
        for (int i = tid; i < RB_YF / 4; i += 256) d4[i] = s4[i];
    }
}

// ---------------------------------------------------------------------------
extern "C" void kernel_launch(void* const* d_in, const int* in_sizes, int n_in,
                              void* d_out, int out_size) {
    const float* x      = (const float*)d_in[0];
    const float* state  = (const float*)d_in[1];
    const float* W_pt   = (const float*)d_in[2];
    const float* b_pt   = (const float*)d_in[3];
    const float* W_last = (const float*)d_in[4];
    const float* b_last = (const float*)d_in[5];
    const float* c      = (const float*)d_in[6];
    const float* h      = (const float*)d_in[7];
    float* out = (float*)d_out;

    static int init_done = 0;
    if (!init_done) {
        cudaFuncSetAttribute(k1_kernel, cudaFuncAttributeMaxDynamicSharedMemorySize,
                             K1_SMEM);
        init_done = 1;
    }

    // K1: gemm1 + coef (no internal dependency)
    k1_kernel<<<307, 256, K1_SMEM>>>(x, W_pt, b_pt, c, h);

    // K2: gemm2, PDL-chained to K1
    {
        cudaLaunchConfig_t cfg = {};
        cfg.gridDim = dim3(BATCH / 64, 2, 2);
        cfg.blockDim = dim3(256, 1, 1);
        cfg.dynamicSmemBytes = 0;
        cfg.stream = 0;
        cudaLaunchAttribute attr[1];
        attr[0].id = cudaLaunchAttributeProgrammaticStreamSerialization;
        attr[0].val.programmaticStreamSerializationAllowed = 1;
        cfg.attrs = attr;
        cfg.numAttrs = 1;
        cudaLaunchKernelEx(&cfg, gemm2_kernel, W_last, b_last);
    }

    // K3: rollout, PDL-chained to K2
    {
        cudaLaunchConfig_t cfg = {};
        cfg.gridDim = dim3(BATCH / RB_BATCH, 1, 1);
        cfg.blockDim = dim3(256, 1, 1);
        cfg.dynamicSmemBytes = RB_SMEM;
        cfg.stream = 0;
        cudaLaunchAttribute attr[1];
        attr[0].id = cudaLaunchAttributeProgrammaticStreamSerialization;
        attr[0].val.programmaticStreamSerializationAllowed = 1;
        cfg.attrs = attr;
        cfg.numAttrs = 1;
        cudaLaunchKernelEx(&cfg, rollout_kernel, (const float*)state, (float*)out);
    }
}

// round 12
// speedup vs baseline: 1.4304x; 1.0054x over previous
#include <cuda_runtime.h>
#include <math.h>

#define BATCH 4096
#define DIN   64
#define HID   256
#define NB    30
#define NDOF  7
#define OUTC  217
#define NS    51
#define DTC   0.002f
#define AZBZ  56.25f
// ln(float(0.998)) and ln(0.985)
#define LNX   (-0.0020019769f)
#define LNLAM (-0.015113638f)
#define BO    (BATCH * OUTC)

__device__ float g_feat[BATCH * HID];
__device__ float g_out217[2 * BO];       // two split-K partials
// coefficients, transposed [ch][slot], slot=(s/7)*8+s%7, duplicated as float2;
// padding slots never written -> stay 0 (static zero-init).
__device__ __align__(16) float2 g_coef_t[33 * 64];

typedef unsigned long long ull;
__device__ __forceinline__ void fma2(ull& d, ull a, ull b) {
    asm("fma.rn.f32x2 %0, %1, %2, %0;" : "+l"(d) : "l"(a), "l"(b));
}
__device__ __forceinline__ float lo32(ull v) { return __uint_as_float((unsigned)v); }
__device__ __forceinline__ float hi32(ull v) { return __uint_as_float((unsigned)(v >> 32)); }

// --- PDL primitives -------------------------------------------------------
__device__ __forceinline__ void pdl_wait() {
    asm volatile("griddepcontrol.wait;" ::: "memory");
}
__device__ __forceinline__ void pdl_trigger() {
    asm volatile("griddepcontrol.launch_dependents;" ::: "memory");
}

// ---------------------------------------------------------------------------
// K1: coef blocks (0..50) + gemm1 tiles (51..306). smem = gemm1's 51200 B.
// coef: thread-per-k convolution, register accumulators, shuffle reduction.
//   delta_{T,n} = dt^2 Sum_{k=1}^{T-1} kw_k * psi_n(x_{T-k}) * x_{T-k}/S_{T-k}
//   kw_k = k * lam^(k-1); gamma uses Sum kw_k; alpha/beta closed-form.
// ---------------------------------------------------------------------------
#define K1_SMEM 51200

__global__ __launch_bounds__(256) void k1_kernel(const float* __restrict__ X,
                                                 const float* __restrict__ Wp,
                                                 const float* __restrict__ bp,
                                                 const float* __restrict__ c,
                                                 const float* __restrict__ h) {
    extern __shared__ __align__(16) float sm[];
    const int tid = threadIdx.x;
    const int bid = blockIdx.x;

    if (bid < 51) {
        // ---- coef block for sample s = bid ----
        float* sc  = sm;          // [32]
        float* sh  = sm + 32;     // [32]
        float* red = sm + 64;     // [8][31]

        if (tid < NB) { sc[tid] = c[tid]; sh[tid] = h[tid]; }
        __syncthreads();

        const int s = bid;
        const int T = s * 10;
        const int slot = (s / 7) * 8 + (s % 7);

        float acc[31];
#pragma unroll
        for (int n = 0; n < 31; n++) acc[n] = 0.f;

        for (int k = tid + 1; k < T; k += 256) {
            float kw = (float)k * __expf(LNLAM * (float)(k - 1));
            float x  = __expf(LNX * (float)(T - k));
            // pass 1: S
            float S = 0.f;
#pragma unroll
            for (int n = 0; n < NB; n++) {
                float d = x - sc[n];
                S += __expf(-sh[n] * d * d);
            }
            float sc2 = kw * x / S;
            // pass 2: accumulate
#pragma unroll
            for (int n = 0; n < NB; n++) {
                float d = x - sc[n];
                acc[n] += __expf(-sh[n] * d * d) * sc2;
            }
            acc[30] += kw;
        }

        // warp reduction
#pragma unroll
        for (int off = 16; off > 0; off >>= 1)
#pragma unroll
            for (int n = 0; n < 31; n++)
                acc[n] += __shfl_down_sync(0xffffffffu, acc[n], off);

        const int wid = tid >> 5, lane = tid & 31;
        if (lane == 0)
#pragma unroll
            for (int n = 0; n < 31; n++) red[wid * 31 + n] = acc[n];
        __syncthreads();

        if (tid < 31) {
            float sum = 0.f;
#pragma unroll
            for (int w = 0; w < 8; w++) sum += red[w * 31 + tid];
            if (tid < NB) {
                float v = (DTC * DTC) * sum;
                g_coef_t[(3 + tid) * 64 + slot] = make_float2(v, v);
            } else {
                float v = AZBZ * (DTC * DTC) * sum;
                g_coef_t[2 * 64 + slot] = make_float2(v, v);
            }
        }
        if (tid == 32) {
            float kwT = (float)T * __expf(LNLAM * (float)(T - 1));
            float v = 0.05f * DTC * kwT;
            g_coef_t[0 * 64 + slot] = make_float2(v, v);
        }
        if (tid == 33) {
            float kwT = (float)T * __expf(LNLAM * (float)(T - 1));
            float v = __expf(LNLAM * (float)T) + 0.015f * kwT;
            g_coef_t[1 * 64 + slot] = make_float2(v, v);
        }
    } else {
        // ---- gemm1 tile: feat = tanh(x @ W_pt + b_pt) ----
        float  (*As)[68] = reinterpret_cast<float(*)[68]>(sm);          // [k][m]
        float2 (*Bs)[66] = reinterpret_cast<float2(*)[66]>(sm + 4352);  // [k][n] dup
        const int t = bid - 51;
        const int bm = (t & 63) * 64;
        const int bn = (t >> 6) * 64;

#pragma unroll
        for (int it = 0; it < 4; it++) {
            int id = tid + it * 256;
            int m = id >> 4, k4 = (id & 15) << 2;
            float4 v = *reinterpret_cast<const float4*>(X + (bm + m) * DIN + k4);
            As[k4 + 0][m] = v.x; As[k4 + 1][m] = v.y;
            As[k4 + 2][m] = v.z; As[k4 + 3][m] = v.w;
        }
#pragma unroll
        for (int it = 0; it < 4; it++) {
            int id = tid + it * 256;
            int k = id >> 4, n4 = (id & 15) << 2;
            float4 v = *reinterpret_cast<const float4*>(Wp + k * HID + bn + n4);
            Bs[k][n4 + 0] = make_float2(v.x, v.x);
            Bs[k][n4 + 1] = make_float2(v.y, v.y);
            Bs[k][n4 + 2] = make_float2(v.z, v.z);
            Bs[k][n4 + 3] = make_float2(v.w, v.w);
        }
        __syncthreads();

        const int ty = tid >> 4, tx = tid & 15;
        ull acc[2][4];
#pragma unroll
        for (int i = 0; i < 2; i++)
#pragma unroll
            for (int j = 0; j < 4; j++) acc[i][j] = 0ull;

#pragma unroll
        for (int k = 0; k < 64; k++) {
            float4 a = *reinterpret_cast<const float4*>(&As[k][ty * 4]);
            ull p0 = *reinterpret_cast<const ull*>(&a.x);
            ull p1 = *reinterpret_cast<const ull*>(&a.z);
#pragma unroll
            for (int j = 0; j < 4; j++) {
                ull b = *reinterpret_cast<const ull*>(&Bs[k][tx + 16 * j]);
                fma2(acc[0][j], p0, b);
                fma2(acc[1][j], p1, b);
            }
        }

#pragma unroll
        for (int j = 0; j < 4; j++) {
            int col = bn + tx + 16 * j;
            float bb = bp[col];
            int r = bm + ty * 4;
            g_feat[(r + 0) * HID + col] = tanhf(lo32(acc[0][j]) + bb);
            g_feat[(r + 1) * HID + col] = tanhf(hi32(acc[0][j]) + bb);
            g_feat[(r + 2) * HID + col] = tanhf(lo32(acc[1][j]) + bb);
            g_feat[(r + 3) * HID + col] = tanhf(hi32(acc[1][j]) + bb);
        }
    }
    pdl_trigger();
}

// ---------------------------------------------------------------------------
// K2: GEMM2 (split-K x2): partial[z] = feat[:, z*128:(z+1)*128] @ Wl[z half].
// B-fragment prefetch before pdl_wait overlaps K1's tail.
// ---------------------------------------------------------------------------
__global__ __launch_bounds__(256) void gemm2_kernel(const float* __restrict__ Wl,
                                                    const float* __restrict__ bl) {
    __shared__ __align__(16) float  As[32][68];   // [k][m]
    __shared__ float2 Bs[32][114];                // [k][n] duplicated
    const int tid = threadIdx.x;
    const int bm = blockIdx.x * 64;
    const int bn = blockIdx.y * 112;
    const int z  = blockIdx.z;
    const int kbase = z * 128;
    const int ty = tid >> 4, tx = tid & 15;

    const int am = tid >> 3;
    const int ak4 = (tid & 7) << 2;

    float4 ra[2];
    float rb[14];

    // B prefetch (input only) — before the PDL wait
#pragma unroll
    for (int it = 0; it < 14; it++) {
        int id = tid + it * 256;
        int kk = id / 112, cc = id - kk * 112;
        rb[it] = (bn + cc < OUTC) ? Wl[(kbase + kk) * OUTC + bn + cc] : 0.f;
    }

    pdl_wait();   // feat (K1 output) valid from here

#pragma unroll
    for (int it = 0; it < 2; it++)
        ra[it] = *reinterpret_cast<const float4*>(
            g_feat + (bm + am + it * 32) * HID + kbase + ak4);

    ull acc[2][7];
#pragma unroll
    for (int i = 0; i < 2; i++)
#pragma unroll
        for (int j = 0; j < 7; j++) acc[i][j] = 0ull;

    for (int k0 = 0; k0 < 128; k0 += 32) {
#pragma unroll
        for (int it = 0; it < 2; it++) {
            int m = am + it * 32;
            As[ak4 + 0][m] = ra[it].x; As[ak4 + 1][m] = ra[it].y;
            As[ak4 + 2][m] = ra[it].z; As[ak4 + 3][m] = ra[it].w;
        }
#pragma unroll
        for (int it = 0; it < 14; it++) {
            int id = tid + it * 256;
            int kk = id / 112, cc = id - kk * 112;
            Bs[kk][cc] = make_float2(rb[it], rb[it]);
        }
        __syncthreads();

        if (k0 + 32 < 128) {
#pragma unroll
            for (int it = 0; it < 2; it++)
                ra[it] = *reinterpret_cast<const float4*>(
                    g_feat + (bm + am + it * 32) * HID + kbase + k0 + 32 + ak4);
#pragma unroll
            for (int it = 0; it < 14; it++) {
                int id = tid + it * 256;
                int kk = id / 112, cc = id - kk * 112;
                rb[it] = (bn + cc < OUTC)
                           ? Wl[(kbase + k0 + 32 + kk) * OUTC + bn + cc] : 0.f;
            }
        }

#pragma unroll
        for (int kk = 0; kk < 32; kk++) {
            float4 a = *reinterpret_cast<const float4*>(&As[kk][ty * 4]);
            ull p0 = *reinterpret_cast<const ull*>(&a.x);
            ull p1 = *reinterpret_cast<const ull*>(&a.z);
#pragma unroll
            for (int j = 0; j < 7; j++) {
                ull b = *reinterpret_cast<const ull*>(&Bs[kk][tx + 16 * j]);
                fma2(acc[0][j], p0, b);
                fma2(acc[1][j], p1, b);
            }
        }
        __syncthreads();
    }

    float* outp = g_out217 + z * BO;
#pragma unroll
    for (int j = 0; j < 7; j++) {
        int col = bn + tx + 16 * j;
        if (col < OUTC) {
            float bb = (z == 0) ? bl[col] : 0.f;
            int r = bm + ty * 4;
            outp[(r + 0) * OUTC + col] = lo32(acc[0][j]) + bb;
            outp[(r + 1) * OUTC + col] = hi32(acc[0][j]) + bb;
            outp[(r + 2) * OUTC + col] = lo32(acc[1][j]) + bb;
            outp[(r + 3) * OUTC + col] = hi32(acc[1][j]) + bb;
        }
    }
    pdl_trigger();
}

// ---------------------------------------------------------------------------
// K3: rollout v5. Block = 8 batches (56 rows), 512 blocks. state prefetched
// before pdl_wait.
// ---------------------------------------------------------------------------
#define RB_BATCH 8
#define RB_ROWS  56
#define RB_OUTF  (RB_BATCH * OUTC)            // 1736
#define RB_YF    (RB_BATCH * NS * NDOF)       // 2856
#define RB_SU    4224
#define RB_SG    (4224 + 1848)                // 6072
#define RB_RG    (6072 + 56)                  // 6128
#define RB_SMEM  ((RB_RG + RB_YF) * 4)        // 35936 bytes

__global__ __launch_bounds__(256) void rollout_kernel(const float* __restrict__ state,
                                                      float* __restrict__ out) {
    extern __shared__ __align__(16) float sm[];
    float2* scfd = reinterpret_cast<float2*>(sm);   // [33][64] slots
    float*  su   = sm + RB_SU;                      // [33][56]
    float*  sg   = sm + RB_SG;                      // [56]
    float*  so   = sm + RB_RG;                      // [1736]
    float*  ybuf = sm + RB_RG;                      // [2856] (after U build)

    const int tid = threadIdx.x;
    const int bbase = blockIdx.x * RB_BATCH;

    // prefetch state (pure harness input) before the PDL wait
    float st0 = state[bbase * NDOF + ((tid < RB_ROWS) ? tid : 0)];

    pdl_wait();   // g_coef_t (K1) and g_out217 (K2) valid

    // scfd fill: pure vector copy, 33*64 float2 = 1056 float4
    {
        const float4* src = reinterpret_cast<const float4*>(g_coef_t);
        float4* dst = reinterpret_cast<float4*>(scfd);
        for (int i = tid; i < 1056; i += 256) dst[i] = src[i];
    }
    // A: contiguous float4 load of both partials, summed
    {
        const float4* p0 = reinterpret_cast<const float4*>(g_out217 + bbase * OUTC);
        const float4* p1 = reinterpret_cast<const float4*>(g_out217 + BO + bbase * OUTC);
        float4* d = reinterpret_cast<float4*>(so);
        for (int i = tid; i < RB_OUTF / 4; i += 256) {
            float4 a = p0[i], b = p1[i];
            d[i] = make_float4(a.x + b.x, a.y + b.y, a.z + b.z, a.w + b.w);
        }
    }
    __syncthreads();

    // y0 / goal / gy0
    if (tid < RB_ROWS) {
        int b = tid / NDOF, dof = tid - b * NDOF;
        float goal = so[b * OUTC + dof];
        su[1 * RB_ROWS + tid] = st0;
        su[2 * RB_ROWS + tid] = goal;
        sg[tid] = goal - st0;
    }
    __syncthreads();

    // U-build
    if (tid < 4 * RB_ROWS) {
        const int g = tid / RB_ROWS;
        const int r = tid - g * RB_ROWS;
        const int b = r / NDOF, dof = r - b * NDOF;
        const float sgr = sg[r];
        const float* wsrc = so + b * OUTC + NDOF + dof * NB + g;
        float* udst = su + (3 + g) * RB_ROWS + r;
#pragma unroll
        for (int i = 0; i < 8; i++) {
            int n = g + 4 * i;
            if (n < NB) udst[4 * i * RB_ROWS] = wsrc[4 * i] * sgr;
        }
    }
    __syncthreads();

    // contraction
    if (tid < 224) {
        const int grp = tid / 28;
        const int rp  = tid - grp * 28;
        const float2* cfb = scfd + grp * 8;
        const float*  ub  = su + rp * 2;

        ull acc[7];
        {
            const float4* c4 = reinterpret_cast<const float4*>(cfb);
            float4 c0 = c4[0], c1 = c4[1], c2 = c4[2], c3 = c4[3];
            acc[0] = *reinterpret_cast<const ull*>(&c0.x);
            acc[1] = *reinterpret_cast<const ull*>(&c0.z);
            acc[2] = *reinterpret_cast<const ull*>(&c1.x);
            acc[3] = *reinterpret_cast<const ull*>(&c1.z);
            acc[4] = *reinterpret_cast<const ull*>(&c2.x);
            acc[5] = *reinterpret_cast<const ull*>(&c2.z);
            acc[6] = *reinterpret_cast<const ull*>(&c3.x);
        }
#pragma unroll
        for (int ch = 1; ch < 33; ch++) {
            ull u = *reinterpret_cast<const ull*>(ub + ch * RB_ROWS);
            const float4* c4 = reinterpret_cast<const float4*>(cfb + ch * 64);
            float4 c0 = c4[0], c1 = c4[1], c2 = c4[2], c3 = c4[3];
            fma2(acc[0], u, *reinterpret_cast<const ull*>(&c0.x));
            fma2(acc[1], u, *reinterpret_cast<const ull*>(&c0.z));
            fma2(acc[2], u, *reinterpret_cast<const ull*>(&c1.x));
            fma2(acc[3], u, *reinterpret_cast<const ull*>(&c1.z));
            fma2(acc[4], u, *reinterpret_cast<const ull*>(&c2.x));
            fma2(acc[5], u, *reinterpret_cast<const ull*>(&c2.z));
            fma2(acc[6], u, *reinterpret_cast<const ull*>(&c3.x));
        }
        __syncthreads();   // so -> ybuf reuse

        const int s0 = grp * 7;
        const int cnt = (grp == 7) ? 2 : 7;
#pragma unroll
        for (int p = 0; p < 2; p++) {
            int row = rp * 2 + p;
            int b = row / NDOF, dof = row - b * NDOF;
            float* yb = ybuf + b * (NS * NDOF) + dof + s0 * NDOF;
#pragma unroll
            for (int q = 0; q < 7; q++) {
                if (q < cnt) {
                    float v = p ? hi32(acc[q]) : lo32(acc[q]);
                    yb[q * NDOF] = v;
                }
            }
        }
    } else {
        __syncthreads();
    }
    __syncthreads();

    // contiguous output store
    {
        const float4* s4 = reinterpret_cast<const float4*>(ybuf);
        float4* d4 = reinterpret_cast<float4*>(out + (size_t)blockIdx.x * RB_YF);
        for (int i = tid; i < RB_YF / 4; i += 256) d4[i] = s4[i];
    }
}

// ---------------------------------------------------------------------------
extern "C" void kernel_launch(void* const* d_in, const int* in_sizes, int n_in,
                              void* d_out, int out_size) {
    const float* x      = (const float*)d_in[0];
    const float* state  = (const float*)d_in[1];
    const float* W_pt   = (const float*)d_in[2];
    const float* b_pt   = (const float*)d_in[3];
    const float* W_last = (const float*)d_in[4];
    const float* b_last = (const float*)d_in[5];
    const float* c      = (const float*)d_in[6];
    const float* h      = (const float*)d_in[7];
    float* out = (float*)d_out;

    static int init_done = 0;
    if (!init_done) {
        cudaFuncSetAttribute(k1_kernel, cudaFuncAttributeMaxDynamicSharedMemorySize,
                             K1_SMEM);
        init_done = 1;
    }

    // K1: coef (blocks 0..50) + gemm1 (blocks 51..306)
    k1_kernel<<<307, 256, K1_SMEM>>>(x, W_pt, b_pt, c, h);

    // K2: gemm2, PDL-chained to K1
    {
        cudaLaunchConfig_t cfg = {};
        cfg.gridDim = dim3(BATCH / 64, 2, 2);
        cfg.blockDim = dim3(256, 1, 1);
        cfg.dynamicSmemBytes = 0;
        cfg.stream = 0;
        cudaLaunchAttribute attr[1];
        attr[0].id = cudaLaunchAttributeProgrammaticStreamSerialization;
        attr[0].val.programmaticStreamSerializationAllowed = 1;
        cfg.attrs = attr;
        cfg.numAttrs = 1;
        cudaLaunchKernelEx(&cfg, gemm2_kernel, W_last, b_last);
    }

    // K3: rollout, PDL-chained to K2
    {
        cudaLaunchConfig_t cfg = {};
        cfg.gridDim = dim3(BATCH / RB_BATCH, 1, 1);
        cfg.blockDim = dim3(256, 1, 1);
        cfg.dynamicSmemBytes = RB_SMEM;
        cfg.stream = 0;
        cudaLaunchAttribute attr[1];
        attr[0].id = cudaLaunchAttributeProgrammaticStreamSerialization;
        attr[0].val.programmaticStreamSerializationAllowed = 1;
        cfg.attrs = attr;
        cfg.numAttrs = 1;
        cudaLaunchKernelEx(&cfg, rollout_kernel, (const float*)state, (float*)out);
    }
}